// round 1
// baseline (speedup 1.0000x reference)
#include <cuda_runtime.h>
#include <math_constants.h>

// Until_74010876444811: out[b,t,x] = min(phi[b,t,x], max(psi[b,t,x], out[b,t-1,x]))
// with out[b,-1,x] = -1e6. Parallel scan over t via the monoid
//   f(c) = min(A, max(B, c));  compose: A' = min(a2, max(b2, A)), B' = max(B, b2).

#define B_  64
#define T_  8192
#define X_  32
#define C_  64              // chunks along T
#define TC_ (T_ / C_)       // 128 time steps per chunk
#define SL_ 8               // t-slices per block
#define PT_ (TC_ / SL_)     // 16 steps per thread
#define LARGE_ 1.0e6f

// scratch: per-chunk aggregates [B, C, 2, X] and incoming carries [B, C, X]
__device__ float g_agg[B_ * C_ * 2 * X_];
__device__ float g_carry[B_ * C_ * X_];

// ---------------- Kernel 1: per-chunk aggregates ----------------
__global__ void __launch_bounds__(256) until_k1(const float* __restrict__ phi,
                                                const float* __restrict__ psi) {
    const int chunk = blockIdx.x;
    const int b     = blockIdx.y;
    const int tid   = threadIdx.x;
    const int x     = tid & 31;
    const int s     = tid >> 5;

    const long base = (long)b * T_ * X_ + (long)(chunk * TC_ + s * PT_) * X_ + x;

    float A  = CUDART_INF_F;
    float Bc = -CUDART_INF_F;
#pragma unroll
    for (int i = 0; i < PT_; i++) {
        float p = phi[base + (long)i * X_];
        float q = psi[base + (long)i * X_];
        A  = fminf(p, fmaxf(q, A));
        Bc = fmaxf(q, Bc);
    }

    __shared__ float sA[SL_][X_];
    __shared__ float sB[SL_][X_];
    sA[s][x] = A;
    sB[s][x] = Bc;
    __syncthreads();

    if (tid < X_) {
        float Ab = CUDART_INF_F;
        float Bb = -CUDART_INF_F;
#pragma unroll
        for (int j = 0; j < SL_; j++) {
            Ab = fminf(sA[j][tid], fmaxf(sB[j][tid], Ab));
            Bb = fmaxf(sB[j][tid], Bb);
        }
        const int o = (b * C_ + chunk) * 2 * X_;
        g_agg[o + tid]      = Ab;
        g_agg[o + X_ + tid] = Bb;
    }
}

// ---------------- Kernel 2: serial scan over chunk aggregates ----------------
__global__ void until_k2() {
    const int idx = blockIdx.x * blockDim.x + threadIdx.x;  // 0..B*X-1
    if (idx >= B_ * X_) return;
    const int b = idx / X_;
    const int x = idx % X_;

    float v = -LARGE_;
#pragma unroll 4
    for (int c = 0; c < C_; c++) {
        g_carry[(b * C_ + c) * X_ + x] = v;
        const int o = (b * C_ + c) * 2 * X_;
        float A = g_agg[o + x];
        float Bv = g_agg[o + X_ + x];
        v = fminf(A, fmaxf(Bv, v));
    }
}

// ---------------- Kernel 3: apply carries, emit outputs ----------------
__global__ void __launch_bounds__(256) until_k3(const float* __restrict__ phi,
                                                const float* __restrict__ psi,
                                                float* __restrict__ out) {
    const int chunk = blockIdx.x;
    const int b     = blockIdx.y;
    const int tid   = threadIdx.x;
    const int x     = tid & 31;
    const int s     = tid >> 5;

    const long base = (long)b * T_ * X_ + (long)(chunk * TC_ + s * PT_) * X_ + x;

    float p[PT_], q[PT_];
    float A  = CUDART_INF_F;
    float Bc = -CUDART_INF_F;
#pragma unroll
    for (int i = 0; i < PT_; i++) {
        p[i] = phi[base + (long)i * X_];
        q[i] = psi[base + (long)i * X_];
        A  = fminf(p[i], fmaxf(q[i], A));
        Bc = fmaxf(q[i], Bc);
    }

    __shared__ float sA[SL_][X_];
    __shared__ float sB[SL_][X_];
    sA[s][x] = A;
    sB[s][x] = Bc;
    __syncthreads();

    // carry at start of this thread's slice: block carry pushed through slices 0..s-1
    float v = g_carry[(b * C_ + chunk) * X_ + x];
#pragma unroll
    for (int j = 0; j < SL_ - 1; j++) {
        if (j < s) v = fminf(sA[j][x], fmaxf(sB[j][x], v));
    }

#pragma unroll
    for (int i = 0; i < PT_; i++) {
        v = fminf(p[i], fmaxf(q[i], v));
        out[base + (long)i * X_] = v;
    }
}

extern "C" void kernel_launch(void* const* d_in, const int* in_sizes, int n_in,
                              void* d_out, int out_size) {
    const float* phi = (const float*)d_in[0];
    const float* psi = (const float*)d_in[1];
    float* out = (float*)d_out;

    dim3 grid(C_, B_);
    until_k1<<<grid, 256>>>(phi, psi);
    until_k2<<<(B_ * X_ + 255) / 256, 256>>>();
    until_k3<<<grid, 256>>>(phi, psi, out);
}

// round 3
// speedup vs baseline: 1.1584x; 1.1584x over previous
#include <cuda_runtime.h>
#include <math_constants.h>

// Until: out[b,t,x] = min(phi[b,t,x], max(psi[b,t,x], out[b,t-1,x])), out[-1] = -1e6.
// Single-pass chained scan (decoupled lookback) over t. Monoid f(v)=min(A,max(B,v)):
//   compose (later∘earlier): A' = min(A2, max(B2, A1)), B' = max(B1, B2).

#define B_   64
#define T_   8192
#define X_   32
#define TC_  128                // time steps per chunk
#define C_   (T_ / TC_)         // 64 chunks
#define NB_  (B_ * C_)          // 4096 blocks
#define SL_  32                 // t-slices per block (one per 8-thread group)
#define PT_  (TC_ / SL_)        // 4 steps per thread
#define LARGE_ 1.0e6f

__device__ float g_A[NB_ * X_];   // chunk aggregate A
__device__ float g_Bv[NB_ * X_];  // chunk aggregate B
__device__ float g_P[NB_ * X_];   // chunk inclusive prefix value
__device__ int   g_flag[NB_];     // 0 = none, 1 = aggregate ready, 2 = prefix ready
__device__ int   g_ticket;

__global__ void until_reset() {
    int i = blockIdx.x * blockDim.x + threadIdx.x;
    if (i < NB_) g_flag[i] = 0;
    if (i == 0) g_ticket = 0;
}

__global__ void __launch_bounds__(256) until_scan(const float* __restrict__ phi,
                                                  const float* __restrict__ psi,
                                                  float* __restrict__ out) {
    __shared__ float sA[SL_][X_];
    __shared__ float sB[SL_][X_];
    __shared__ float sC[SL_][X_];
    __shared__ int s_tic;

    const int tid = threadIdx.x;
    if (tid == 0) s_tic = atomicAdd(&g_ticket, 1);
    __syncthreads();
    const int v  = s_tic;
    const int b  = v % B_;       // breadth-first over chunks: all chunk-c blocks
    const int c  = v / B_;       // are ticketed before any chunk-(c+1) block
    const int bc = b * C_ + c;

    const int xq = (tid & 7) * 4;     // 4 consecutive x per thread
    const int s  = tid >> 3;          // slice 0..31

    const size_t base = (size_t)b * T_ * X_ + (size_t)(c * TC_ + s * PT_) * X_ + xq;
    const float4* pp = (const float4*)(phi + base);
    const float4* qq = (const float4*)(psi + base);

    float4 p[PT_], q[PT_];
    float4 A  = make_float4( CUDART_INF_F,  CUDART_INF_F,  CUDART_INF_F,  CUDART_INF_F);
    float4 Bc = make_float4(-CUDART_INF_F, -CUDART_INF_F, -CUDART_INF_F, -CUDART_INF_F);
#pragma unroll
    for (int i = 0; i < PT_; i++) {
        p[i] = pp[i * (X_ / 4)];
        q[i] = qq[i * (X_ / 4)];
        A.x = fminf(p[i].x, fmaxf(q[i].x, A.x));  Bc.x = fmaxf(q[i].x, Bc.x);
        A.y = fminf(p[i].y, fmaxf(q[i].y, A.y));  Bc.y = fmaxf(q[i].y, Bc.y);
        A.z = fminf(p[i].z, fmaxf(q[i].z, A.z));  Bc.z = fmaxf(q[i].z, Bc.z);
        A.w = fminf(p[i].w, fmaxf(q[i].w, A.w));  Bc.w = fmaxf(q[i].w, Bc.w);
    }
    sA[s][xq + 0] = A.x;  sA[s][xq + 1] = A.y;  sA[s][xq + 2] = A.z;  sA[s][xq + 3] = A.w;
    sB[s][xq + 0] = Bc.x; sB[s][xq + 1] = Bc.y; sB[s][xq + 2] = Bc.z; sB[s][xq + 3] = Bc.w;
    __syncthreads();

    if (tid < 32) {
        const int x = tid;
        // fold 32 slice aggregates -> block aggregate
        float Ab =  CUDART_INF_F;
        float Bb = -CUDART_INF_F;
#pragma unroll
        for (int j = 0; j < SL_; j++) {
            Ab = fminf(sA[j][x], fmaxf(sB[j][x], Ab));
            Bb = fmaxf(sB[j][x], Bb);
        }

        // Publish aggregate (flag=1) ONLY for c>0. Chunk 0 of each batch goes
        // straight to flag=2 below, so lookback can never walk past a batch
        // boundary (it always terminates at a flag==2 chunk at or before c=0).
        if (c > 0) {
            g_A[bc * X_ + x]  = Ab;
            g_Bv[bc * X_ + x] = Bb;
            __threadfence();
            __syncwarp();
            if (x == 0) *(volatile int*)&g_flag[bc] = 1;
        }

        // decoupled lookback for incoming carry
        float vin;
        if (c == 0) {
            vin = -LARGE_;
        } else {
            float accA =  CUDART_INF_F;
            float accB = -CUDART_INF_F;
            int j = bc - 1;               // chunk c-1 of same b
            while (true) {
                int f;
                do { f = *(volatile int*)&g_flag[j]; } while (f == 0);
                __threadfence();
                if (f == 2) {
                    vin = fminf(accA, fmaxf(accB, g_P[j * X_ + x]));
                    break;
                }
                float Aj = g_A[j * X_ + x];
                float Bj = g_Bv[j * X_ + x];
                accA = fminf(accA, fmaxf(accB, Aj));
                accB = fmaxf(accB, Bj);
                j--;
            }
        }

        // per-slice incoming carries + publish inclusive prefix
        float vv = vin;
#pragma unroll
        for (int j = 0; j < SL_; j++) {
            sC[j][x] = vv;
            vv = fminf(sA[j][x], fmaxf(sB[j][x], vv));
        }
        g_P[bc * X_ + x] = vv;
        __threadfence();
        __syncwarp();
        if (x == 0) *(volatile int*)&g_flag[bc] = 2;
    }
    __syncthreads();

    float4 vc = make_float4(sC[s][xq], sC[s][xq + 1], sC[s][xq + 2], sC[s][xq + 3]);
    float4* oo = (float4*)(out + base);
#pragma unroll
    for (int i = 0; i < PT_; i++) {
        vc.x = fminf(p[i].x, fmaxf(q[i].x, vc.x));
        vc.y = fminf(p[i].y, fmaxf(q[i].y, vc.y));
        vc.z = fminf(p[i].z, fmaxf(q[i].z, vc.z));
        vc.w = fminf(p[i].w, fmaxf(q[i].w, vc.w));
        oo[i * (X_ / 4)] = vc;
    }
}

extern "C" void kernel_launch(void* const* d_in, const int* in_sizes, int n_in,
                              void* d_out, int out_size) {
    const float* phi = (const float*)d_in[0];
    const float* psi = (const float*)d_in[1];
    float* out = (float*)d_out;

    until_reset<<<(NB_ + 255) / 256, 256>>>();
    until_scan<<<NB_, 256>>>(phi, psi, out);
}

// round 4
// speedup vs baseline: 1.5039x; 1.2982x over previous
#include <cuda_runtime.h>
#include <math_constants.h>

// Until: out[b,t,x] = min(phi[b,t,x], max(psi[b,t,x], out[b,t-1,x])), out[-1] = -1e6.
// Single-pass chained scan (decoupled lookback) over t. Monoid f(v)=min(A,max(B,v)):
//   compose (later∘earlier): A' = min(A2, max(B2, A1)), B' = max(B1, B2).
// R4: streaming phase-1 (no register residency) + L2 reload in phase-2 to keep
// register count low -> high occupancy -> memory pipe stays busy during the
// fold/lookback serial sections.

#define B_   64
#define T_   8192
#define X_   32
#define TC_  256                // time steps per chunk
#define C_   (T_ / TC_)         // 32 chunks
#define NB_  (B_ * C_)          // 2048 blocks
#define SL_  32                 // t-slices per block
#define PT_  (TC_ / SL_)        // 8 steps per thread
#define LARGE_ 1.0e6f

__device__ float g_A[NB_ * X_];   // chunk aggregate A
__device__ float g_Bv[NB_ * X_];  // chunk aggregate B
__device__ float g_P[NB_ * X_];   // chunk inclusive prefix value
__device__ int   g_flag[NB_];     // 0 = none, 1 = aggregate ready, 2 = prefix ready
__device__ int   g_ticket;

__global__ void until_reset() {
    int i = blockIdx.x * blockDim.x + threadIdx.x;
    if (i < NB_) g_flag[i] = 0;
    if (i == 0) g_ticket = 0;
}

__global__ void __launch_bounds__(256) until_scan(const float* __restrict__ phi,
                                                  const float* __restrict__ psi,
                                                  float* __restrict__ out) {
    __shared__ float sA[SL_][X_];
    __shared__ float sB[SL_][X_];
    __shared__ float sC[SL_][X_];
    __shared__ int s_tic;

    const int tid = threadIdx.x;
    if (tid == 0) s_tic = atomicAdd(&g_ticket, 1);
    __syncthreads();
    const int v  = s_tic;
    const int b  = v % B_;       // breadth-first over chunks
    const int c  = v / B_;
    const int bc = b * C_ + c;

    const int xq = (tid & 7) * 4;     // 4 consecutive x per thread
    const int s  = tid >> 3;          // slice 0..31

    const size_t base = (size_t)b * T_ * X_ + (size_t)(c * TC_ + s * PT_) * X_ + xq;
    const float4* pp = (const float4*)(phi + base);
    const float4* qq = (const float4*)(psi + base);

    // ---------- phase 1: streaming aggregate (no data kept in registers) ----------
    float4 A  = make_float4( CUDART_INF_F,  CUDART_INF_F,  CUDART_INF_F,  CUDART_INF_F);
    float4 Bc = make_float4(-CUDART_INF_F, -CUDART_INF_F, -CUDART_INF_F, -CUDART_INF_F);
#pragma unroll
    for (int i = 0; i < PT_; i++) {
        float4 p = pp[i * (X_ / 4)];
        float4 q = qq[i * (X_ / 4)];
        A.x = fminf(p.x, fmaxf(q.x, A.x));  Bc.x = fmaxf(q.x, Bc.x);
        A.y = fminf(p.y, fmaxf(q.y, A.y));  Bc.y = fmaxf(q.y, Bc.y);
        A.z = fminf(p.z, fmaxf(q.z, A.z));  Bc.z = fmaxf(q.z, Bc.z);
        A.w = fminf(p.w, fmaxf(q.w, A.w));  Bc.w = fmaxf(q.w, Bc.w);
    }
    sA[s][xq + 0] = A.x;  sA[s][xq + 1] = A.y;  sA[s][xq + 2] = A.z;  sA[s][xq + 3] = A.w;
    sB[s][xq + 0] = Bc.x; sB[s][xq + 1] = Bc.y; sB[s][xq + 2] = Bc.z; sB[s][xq + 3] = Bc.w;
    __syncthreads();

    // ---------- fold + decoupled lookback (warp 0, lane = x) ----------
    if (tid < 32) {
        const int x = tid;
        float Ab =  CUDART_INF_F;
        float Bb = -CUDART_INF_F;
#pragma unroll
        for (int j = 0; j < SL_; j++) {
            Ab = fminf(sA[j][x], fmaxf(sB[j][x], Ab));
            Bb = fmaxf(sB[j][x], Bb);
        }

        // Publish aggregate (flag=1) ONLY for c>0: chunk 0 goes straight to
        // flag=2, so lookback never crosses a batch boundary.
        if (c > 0) {
            g_A[bc * X_ + x]  = Ab;
            g_Bv[bc * X_ + x] = Bb;
            __threadfence();
            __syncwarp();
            if (x == 0) *(volatile int*)&g_flag[bc] = 1;
        }

        float vin;
        if (c == 0) {
            vin = -LARGE_;
        } else {
            float accA =  CUDART_INF_F;
            float accB = -CUDART_INF_F;
            int j = bc - 1;
            while (true) {
                int f;
                do { f = *(volatile int*)&g_flag[j]; } while (f == 0);
                __threadfence();
                if (f == 2) {
                    vin = fminf(accA, fmaxf(accB, g_P[j * X_ + x]));
                    break;
                }
                float Aj = g_A[j * X_ + x];
                float Bj = g_Bv[j * X_ + x];
                accA = fminf(accA, fmaxf(accB, Aj));
                accB = fmaxf(accB, Bj);
                j--;
            }
        }

        float vv = vin;
#pragma unroll
        for (int j = 0; j < SL_; j++) {
            sC[j][x] = vv;
            vv = fminf(sA[j][x], fmaxf(sB[j][x], vv));
        }
        g_P[bc * X_ + x] = vv;
        __threadfence();
        __syncwarp();
        if (x == 0) *(volatile int*)&g_flag[bc] = 2;
    }
    __syncthreads();

    // ---------- phase 2: reload (L2 hits), apply carry, stream out ----------
    float4 vc = make_float4(sC[s][xq], sC[s][xq + 1], sC[s][xq + 2], sC[s][xq + 3]);
    float4* oo = (float4*)(out + base);
#pragma unroll
    for (int i = 0; i < PT_; i++) {
        float4 p = __ldcs(&pp[i * (X_ / 4)]);
        float4 q = __ldcs(&qq[i * (X_ / 4)]);
        vc.x = fminf(p.x, fmaxf(q.x, vc.x));
        vc.y = fminf(p.y, fmaxf(q.y, vc.y));
        vc.z = fminf(p.z, fmaxf(q.z, vc.z));
        vc.w = fminf(p.w, fmaxf(q.w, vc.w));
        __stcs(&oo[i * (X_ / 4)], vc);
    }
}

extern "C" void kernel_launch(void* const* d_in, const int* in_sizes, int n_in,
                              void* d_out, int out_size) {
    const float* phi = (const float*)d_in[0];
    const float* psi = (const float*)d_in[1];
    float* out = (float*)d_out;

    until_reset<<<(NB_ + 255) / 256, 256>>>();
    until_scan<<<NB_, 256>>>(phi, psi, out);
}